// round 13
// baseline (speedup 1.0000x reference)
#include <cuda_runtime.h>
#include <cuda_bf16.h>
#include <cuda_fp16.h>
#include <stdint.h>

// Problem constants
#define BB 8
#define NN 2048
#define HH 512
#define NSEL 9
#define NLAYERS 3
#define LN_EPS 1e-5f

#define ADJ_WORDS 64
#define MTOT (BB*NN)        // 16384 rows
#define MAXDEG 96

// ---------------- device scratch ----------------
__device__ uint32_t g_adj[BB * NN * ADJ_WORDS];     // 4 MB
__device__ float4   g_x4[BB * NN * (HH/4)];         // 32 MB current x (fp32, residual path)
__device__ __half   g_xh[2][MTOT * HH];             // 2 x 16 MB fp16 shadow (double-buffered!)
__device__ __half   g_Wh[NLAYERS * HH * HH];        // W^T fp16  [l][n][k]

// ---------------- helpers (sm_80+ only) ----------------
__device__ __forceinline__ uint32_t smem_u32(const void* p) {
    uint32_t a;
    asm("{ .reg .u64 t; cvta.to.shared.u64 t, %1; cvt.u32.u64 %0, t; }" : "=r"(a) : "l"(p));
    return a;
}
__device__ __forceinline__ void ldm_x4(uint32_t* r, uint32_t addr) {
    asm volatile("ldmatrix.sync.aligned.m8n8.x4.shared.b16 {%0,%1,%2,%3}, [%4];"
                 : "=r"(r[0]), "=r"(r[1]), "=r"(r[2]), "=r"(r[3]) : "r"(addr));
}
__device__ __forceinline__ void mma_fp16(float* c, const uint32_t* a, const uint32_t* b) {
    asm volatile("mma.sync.aligned.m16n8k16.row.col.f32.f16.f16.f32 "
                 "{%0,%1,%2,%3}, {%4,%5,%6,%7}, {%8,%9}, {%0,%1,%2,%3};"
                 : "+f"(c[0]), "+f"(c[1]), "+f"(c[2]), "+f"(c[3])
                 : "r"(a[0]), "r"(a[1]), "r"(a[2]), "r"(a[3]), "r"(b[0]), "r"(b[1]));
}
__device__ __forceinline__ void cpa16(uint32_t s, const void* g) {
    asm volatile("cp.async.cg.shared.global [%0], [%1], 16;" :: "r"(s), "l"(g));
}

// ---------------- kernel 0: merged setup ----------------
// blocks [0,128): zero g_adj
// blocks [128,896): convw (3*16*16 tiles)
// blocks [896,1920): node_features fp32 -> g_xh[0] fp16
__global__ void __launch_bounds__(256) setup_kernel(const float* __restrict__ W,
                                                    const float4* __restrict__ nf4) {
    __shared__ float tile[32][33];
    if (blockIdx.x < 128) {
        for (int j = blockIdx.x * 256 + threadIdx.x; j < BB * NN * ADJ_WORDS; j += 128 * 256)
            g_adj[j] = 0u;
        return;
    }
    if (blockIdx.x >= 896) {
        const int base = (blockIdx.x - 896) * 256 + threadIdx.x;
        for (int j = base; j < MTOT * (HH / 4); j += 1024 * 256) {
            const float4 v = nf4[j];
            ((__half2*)g_xh[0])[2 * j]     = __floats2half2_rn(v.x, v.y);
            ((__half2*)g_xh[0])[2 * j + 1] = __floats2half2_rn(v.z, v.w);
        }
        return;
    }
    const int bid = blockIdx.x - 128;
    const int l   = bid >> 8;
    const int rem = bid & 255;
    const int n0  = (rem & 15) * 32;
    const int k0  = (rem >> 4) * 32;
    const int tx  = threadIdx.x & 31;
    const int ty  = threadIdx.x >> 5;

    #pragma unroll
    for (int i = 0; i < 4; i++)
        tile[ty + i * 8][tx] = W[(size_t)l * HH * HH + (size_t)(k0 + ty + i * 8) * HH + n0 + tx];
    __syncthreads();

    #pragma unroll
    for (int i = 0; i < 4; i++) {
        const int n = n0 + ty + i * 8;
        const int k = k0 + tx;
        g_Wh[(size_t)l * HH * HH + (size_t)n * HH + k] = __float2half_rn(tile[tx][ty + i * 8]);
    }
}

// ---------------- kernel 1: warp-per-row top-k + adjacency build ----------------
__global__ void __launch_bounds__(256) topk_adj_kernel(const float2* __restrict__ coords) {
    __shared__ float2 sc[NN];
    const int b    = blockIdx.y;
    const int tid  = threadIdx.x;
    const int lane = tid & 31;
    const int wrp  = tid >> 5;
    const int n    = blockIdx.x * 8 + wrp;

    const float2* cb = coords + (size_t)b * NN;
    for (int i = tid; i < NN; i += 256) sc[i] = cb[i];
    __syncthreads();

    const float xn = sc[n].x, yn = sc[n].y;
    const float sqn = __fadd_rn(__fmul_rn(xn, xn), __fmul_rn(yn, yn));

    unsigned long long top[NSEL];
    #pragma unroll
    for (int j = 0; j < NSEL; j++) top[j] = ~0ull;

    for (int m = lane; m < NN; m += 32) {
        const float xm = sc[m].x, ym = sc[m].y;
        const float sqm = __fadd_rn(__fmul_rn(xm, xm), __fmul_rn(ym, ym));
        const float dot = __fmaf_rn(yn, ym, __fmul_rn(xn, xm));
        const float d2  = __fsub_rn(__fadd_rn(sqn, sqm), __fmul_rn(2.0f, dot));
        uint32_t fb = __float_as_uint(d2);
        fb = (fb & 0x80000000u) ? ~fb : (fb | 0x80000000u);
        const unsigned long long k = ((unsigned long long)fb << 32) | (uint32_t)m;
        if (k < top[NSEL - 1]) {
            top[NSEL - 1] = k;
            #pragma unroll
            for (int j = NSEL - 1; j > 0; j--) {
                if (top[j] < top[j - 1]) {
                    unsigned long long t = top[j]; top[j] = top[j - 1]; top[j - 1] = t;
                }
            }
        }
    }

    int p = 0;
    for (int r = 0; r < NSEL; r++) {
        unsigned long long cand = (p < NSEL) ? top[p] : ~0ull;
        unsigned long long mn = cand;
        #pragma unroll
        for (int off = 16; off > 0; off >>= 1) {
            unsigned long long o = __shfl_xor_sync(0xffffffffu, mn, off);
            mn = (o < mn) ? o : mn;
        }
        if (cand == mn) p++;
        if (r > 0 && lane == 0) {
            const int m = (int)(mn & 0xffffffffu);
            atomicOr(&g_adj[((size_t)b * NN + n) * ADJ_WORDS + (m >> 5)], 1u << (m & 31));
            atomicOr(&g_adj[((size_t)b * NN + m) * ADJ_WORDS + (n >> 5)], 1u << (n & 31));
        }
    }
}

// ---------------- kernel 2: FUSED agg + fp16 GEMM + bias + LN + ReLU + residual ----
// CTA: 64 rows x 512 cols, 512 threads = 16 warps (2 M x 8 N), warp tile 32x64.
// Prologue: decode adj + gather-aggregate fp16 x (READ plane) into smem A-tile.
// Mainloop: 2-stage cp.async W pipeline, K-chunk 32, A from resident smem.
// Epilogue: writes fp32 out + fp16 shadow into the WRITE plane (!= read plane).
#define SA       0                      // A: 64 rows x 520 halves = 66560 B
#define A_STRIDE 1040
#define SW       66560                  // W stages: 2 x (512 x 80 B) = 81920
#define WSTG     40960
#define SL       148480                 // neighbor lists: 64 x 96 ints = 24576
#define SDEG     173056                 // 64 ints (+pad) = 256
#define SG_BIAS  173312                 // 512 f
#define SG_GAMMA 175360
#define SG_BETA  177408
#define SG_PSUM  179456                 // 64 x 8 f
#define SG_PSQ   181504
#define SG_MU    183552                 // 64 f
#define SG_RS    183808
#define SM_TOTAL2 184064

__global__ void __launch_bounds__(512, 1) gemm_fused_kernel(
    const __half* __restrict__ Wh,
    const float* __restrict__ bl, const float* __restrict__ gl, const float* __restrict__ btl,
    const float* __restrict__ resid, float* __restrict__ out,
    const __half* __restrict__ xin,    // READ plane
    __half* __restrict__ outh)         // WRITE plane (different buffer!)
{
    extern __shared__ char smem[];
    const uint32_t sbase = smem_u32(smem);
    const int tid  = threadIdx.x;
    const int lane = tid & 31;
    const int wid  = tid >> 5;
    const int mwarp = wid >> 3;        // 0..1
    const int nwarp = wid & 7;         // 0..7
    const int row0 = blockIdx.x * 64;
    const int b    = row0 / NN;        // batch (tiles never straddle batches)
    const int n0   = row0 % NN;

    ((float*)(smem + SG_BIAS))[tid]  = __ldg(&bl[tid]);
    ((float*)(smem + SG_GAMMA))[tid] = __ldg(&gl[tid]);
    ((float*)(smem + SG_BETA))[tid]  = __ldg(&btl[tid]);

    #define LOAD_W(chk, stg) do {                                                  \
        const int kc0_ = (chk) * 32;                                               \
        const uint32_t sb_ = sbase + SW + (stg) * WSTG;                            \
        _Pragma("unroll")                                                          \
        for (int i_ = 0; i_ < 4; i_++) {                                           \
            const int idx_ = tid + i_ * 512;                                       \
            const int r_ = idx_ >> 2, seg_ = idx_ & 3;                             \
            cpa16(sb_ + r_ * 80 + seg_ * 16,                                       \
                  Wh + (size_t)r_ * HH + kc0_ + seg_ * 8);                         \
        }                                                                          \
        asm volatile("cp.async.commit_group;");                                    \
    } while (0)

    // W chunk 0 in flight during the whole agg prologue
    LOAD_W(0, 0);

    // ---- prologue phase A: decode adjacency (1 thread per row) ----
    int* s_list = (int*)(smem + SL);
    int* s_deg  = (int*)(smem + SDEG);
    if (tid < 64) {
        const uint32_t* ar = &g_adj[((size_t)b * NN + n0 + tid) * ADJ_WORDS];
        int dg = 0;
        #pragma unroll 8
        for (int w = 0; w < ADJ_WORDS; w++) {
            uint32_t bits = __ldg(&ar[w]);
            while (bits) {
                const int bit = __ffs(bits) - 1;
                bits &= bits - 1;
                if (dg < MAXDEG) s_list[tid * MAXDEG + dg] = (w << 5) + bit;
                dg++;
            }
        }
        s_deg[tid] = (dg < MAXDEG) ? dg : MAXDEG;
    }
    __syncthreads();

    // ---- prologue phase B: gather-aggregate (warp = 4 rows, lane = 16 feats) ----
    {
        const uint2* xb = (const uint2*)(xin + (size_t)b * NN * HH);
        #pragma unroll
        for (int rr = 0; rr < 4; rr++) {
            const int row = wid * 4 + rr;
            const int dg  = s_deg[row];
            float acc[16];
            #pragma unroll
            for (int q = 0; q < 16; q++) acc[q] = 0.f;
            for (int i = 0; i < dg; i++) {
                const int m = s_list[row * MAXDEG + i];
                #pragma unroll
                for (int s = 0; s < 4; s++) {
                    const uint2 v = __ldg(&xb[(size_t)m * (HH/4) + lane + s * 32]);
                    const float2 f01 = __half22float2(*(const __half2*)&v.x);
                    const float2 f23 = __half22float2(*(const __half2*)&v.y);
                    acc[s*4+0] += f01.x; acc[s*4+1] += f01.y;
                    acc[s*4+2] += f23.x; acc[s*4+3] += f23.y;
                }
            }
            #pragma unroll
            for (int s = 0; s < 4; s++) {
                uint2 pk;
                *(__half2*)&pk.x = __floats2half2_rn(acc[s*4+0], acc[s*4+1]);
                *(__half2*)&pk.y = __floats2half2_rn(acc[s*4+2], acc[s*4+3]);
                *(uint2*)(smem + SA + row * A_STRIDE + (lane + s * 32) * 8) = pk;
            }
        }
    }
    __syncthreads();   // A-tile ready for all warps

    float c[16][4];
    #pragma unroll
    for (int f = 0; f < 16; f++)
        #pragma unroll
        for (int q = 0; q < 4; q++) c[f][q] = 0.f;

    // ---- mainloop: 16 K-chunks of 32, 2-stage W pipeline (R10 pattern) ----
    for (int chk = 0; chk < 16; chk++) {
        if (chk + 1 < 16) {
            LOAD_W(chk + 1, (chk + 1) & 1);
            asm volatile("cp.async.wait_group 1;");
        } else {
            asm volatile("cp.async.wait_group 0;");
        }
        __syncthreads();

        const uint32_t swb = sbase + SW + (chk & 1) * WSTG;
        const uint32_t ab  = sbase + SA + chk * 64;     // 32 halves = 64 B per chunk
        #pragma unroll
        for (int ks = 0; ks < 2; ks++) {
            const int amat = lane >> 3;
            const int arow = (amat & 1) * 8 + (lane & 7);
            const int akb  = (ks * 16 + (amat >> 1) * 8) * 2;
            uint32_t ah[2][4], bb[8][2];
            #pragma unroll
            for (int mi = 0; mi < 2; mi++) {
                const uint32_t ra = mwarp * 32 + mi * 16 + arow;
                ldm_x4(ah[mi], ab + ra * A_STRIDE + akb);
            }
            const int bmat = lane >> 3;
            const int bn   = (bmat >> 1) * 8 + (lane & 7);
            const int bkb  = (ks * 16 + (bmat & 1) * 8) * 2;
            #pragma unroll
            for (int g = 0; g < 4; g++) {
                uint32_t r[4];
                ldm_x4(r, swb + (uint32_t)(nwarp * 64 + g * 16 + bn) * 80 + bkb);
                bb[g*2][0] = r[0]; bb[g*2][1] = r[1];
                bb[g*2+1][0] = r[2]; bb[g*2+1][1] = r[3];
            }
            #pragma unroll
            for (int mi = 0; mi < 2; mi++)
                #pragma unroll
                for (int ni = 0; ni < 8; ni++) mma_fp16(c[mi*8+ni], ah[mi], bb[ni]);
        }
        __syncthreads();
    }

    // ---------------- epilogue: bias + LN + ReLU + residual + fp16 shadow ----
    float* bias_s  = (float*)(smem + SG_BIAS);
    float* gamma_s = (float*)(smem + SG_GAMMA);
    float* beta_s  = (float*)(smem + SG_BETA);
    float* psum_s  = (float*)(smem + SG_PSUM);
    float* psq_s   = (float*)(smem + SG_PSQ);
    float* mu_s    = (float*)(smem + SG_MU);
    float* rs_s    = (float*)(smem + SG_RS);

    float ps[2][2] = {{0.f,0.f},{0.f,0.f}};
    float pq[2][2] = {{0.f,0.f},{0.f,0.f}};
    #pragma unroll
    for (int mi = 0; mi < 2; mi++)
        #pragma unroll
        for (int ni = 0; ni < 8; ni++) {
            const int f = mi*8 + ni;
            #pragma unroll
            for (int h = 0; h < 2; h++)
                #pragma unroll
                for (int j = 0; j < 2; j++) {
                    const int col = nwarp*64 + ni*8 + (lane & 3)*2 + j;
                    const float v = c[f][h*2+j] + bias_s[col];
                    c[f][h*2+j] = v;
                    ps[mi][h] += v;
                    pq[mi][h] += v * v;
                }
        }
    #pragma unroll
    for (int mi = 0; mi < 2; mi++)
        #pragma unroll
        for (int h = 0; h < 2; h++) {
            #pragma unroll
            for (int off = 1; off < 4; off <<= 1) {
                ps[mi][h] += __shfl_xor_sync(0xffffffffu, ps[mi][h], off);
                pq[mi][h] += __shfl_xor_sync(0xffffffffu, pq[mi][h], off);
            }
        }
    if ((lane & 3) == 0) {
        #pragma unroll
        for (int mi = 0; mi < 2; mi++)
            #pragma unroll
            for (int h = 0; h < 2; h++) {
                const int rl = mwarp*32 + mi*16 + h*8 + (lane >> 2);
                psum_s[rl*8 + nwarp] = ps[mi][h];
                psq_s [rl*8 + nwarp] = pq[mi][h];
            }
    }
    __syncthreads();
    if (tid < 64) {
        float s = 0.f, q = 0.f;
        #pragma unroll
        for (int w = 0; w < 8; w++) { s += psum_s[tid*8 + w]; q += psq_s[tid*8 + w]; }
        const float mu = s * (1.0f / HH);
        const float var = q * (1.0f / HH) - mu * mu;
        mu_s[tid] = mu;
        rs_s[tid] = rsqrtf(var + LN_EPS);
    }
    __syncthreads();

    #pragma unroll
    for (int mi = 0; mi < 2; mi++)
        #pragma unroll
        for (int h = 0; h < 2; h++) {
            const int rl = mwarp*32 + mi*16 + h*8 + (lane >> 2);
            const int grow = row0 + rl;
            const float mu = mu_s[rl];
            const float rs = rs_s[rl];
            #pragma unroll
            for (int ni = 0; ni < 8; ni++) {
                const int f = mi*8 + ni;
                const int col = nwarp*64 + ni*8 + (lane & 3)*2;
                float2 o;
                o.x = fmaxf((c[f][h*2+0] - mu) * rs * gamma_s[col]   + beta_s[col],   0.f);
                o.y = fmaxf((c[f][h*2+1] - mu) * rs * gamma_s[col+1] + beta_s[col+1], 0.f);
                if (resid != nullptr) {
                    const float2 rv = __ldg((const float2*)&resid[(size_t)grow * HH + col]);
                    o.x += rv.x; o.y += rv.y;
                }
                *(float2*)&out[(size_t)grow * HH + col] = o;
                *(__half2*)&outh[(size_t)grow * HH + col] = __floats2half2_rn(o.x, o.y);
            }
        }
}

// ---------------- launcher ----------------
extern "C" void kernel_launch(void* const* d_in, const int* in_sizes, int n_in,
                              void* d_out, int out_size) {
    (void)in_sizes; (void)n_in; (void)out_size;
    const float*  node_features = (const float*)d_in[0];   // [8,2048,512]
    const float2* coords        = (const float2*)d_in[1];  // [8,2048,2]
    const float*  W             = (const float*)d_in[2];   // [3,512,512]
    const float*  bvec          = (const float*)d_in[3];   // [3,512]
    const float*  gamma         = (const float*)d_in[4];   // [3,512]
    const float*  beta          = (const float*)d_in[5];   // [3,512]
    float*        outp          = (float*)d_out;           // [8,2048,512]

    float4* gx;  cudaGetSymbolAddress((void**)&gx,  g_x4);
    __half *wh, *xh0;
    cudaGetSymbolAddress((void**)&wh, g_Wh);
    cudaGetSymbolAddress((void**)&xh0, g_xh);
    __half* xplane[2] = { xh0, xh0 + (size_t)MTOT * HH };

    cudaFuncSetAttribute(gemm_fused_kernel, cudaFuncAttributeMaxDynamicSharedMemorySize, SM_TOTAL2);

    setup_kernel<<<1920, 256>>>(W, (const float4*)node_features);
    topk_adj_kernel<<<dim3(NN / 8, BB), 256>>>(coords);

    for (int l = 0; l < NLAYERS; l++) {
        const float* resid = (l == 0) ? nullptr : (const float*)gx;
        float* out = (l == NLAYERS - 1) ? outp : (float*)gx;
        gemm_fused_kernel<<<MTOT / 64, 512, SM_TOTAL2>>>(
            wh + (size_t)l * HH * HH,
            bvec + (size_t)l * HH, gamma + (size_t)l * HH, beta + (size_t)l * HH,
            resid, out,
            xplane[l & 1],          // read plane
            xplane[(l + 1) & 1]);   // write plane (different buffer)
    }
}

// round 14
// speedup vs baseline: 1.7423x; 1.7423x over previous
#include <cuda_runtime.h>
#include <cuda_bf16.h>
#include <cuda_fp16.h>
#include <stdint.h>

// Problem constants
#define BB 8
#define NN 2048
#define HH 512
#define NSEL 9
#define NLAYERS 3
#define LN_EPS 1e-5f

#define ADJ_WORDS 64
#define MTOT (BB*NN)        // 16384 rows
#define GRID 16             // 16x16 spatial bins
#define CW (1.0f/16.0f)

// ---------------- device scratch ----------------
__device__ uint32_t g_adj[BB * NN * ADJ_WORDS];     // 4 MB
__device__ float4   g_x4[BB * NN * (HH/4)];         // 32 MB current x (fp32, residual path)
__device__ __half   g_Ah[MTOT * HH];                // 16 MB agg fp16
__device__ __half   g_Wh[NLAYERS * HH * HH];        // W^T fp16  [l][n][k]
__device__ int      g_bin_start[BB][257];
__device__ uint16_t g_bin_ids[BB][NN];

// ---------------- helpers (sm_80+ only) ----------------
__device__ __forceinline__ uint32_t smem_u32(const void* p) {
    uint32_t a;
    asm("{ .reg .u64 t; cvta.to.shared.u64 t, %1; cvt.u32.u64 %0, t; }" : "=r"(a) : "l"(p));
    return a;
}
__device__ __forceinline__ void ldm_x4(uint32_t* r, uint32_t addr) {
    asm volatile("ldmatrix.sync.aligned.m8n8.x4.shared.b16 {%0,%1,%2,%3}, [%4];"
                 : "=r"(r[0]), "=r"(r[1]), "=r"(r[2]), "=r"(r[3]) : "r"(addr));
}
__device__ __forceinline__ void mma_fp16(float* c, const uint32_t* a, const uint32_t* b) {
    asm volatile("mma.sync.aligned.m16n8k16.row.col.f32.f16.f16.f32 "
                 "{%0,%1,%2,%3}, {%4,%5,%6,%7}, {%8,%9}, {%0,%1,%2,%3};"
                 : "+f"(c[0]), "+f"(c[1]), "+f"(c[2]), "+f"(c[3])
                 : "r"(a[0]), "r"(a[1]), "r"(a[2]), "r"(a[3]), "r"(b[0]), "r"(b[1]));
}
__device__ __forceinline__ void cpa16(uint32_t s, const void* g) {
    asm volatile("cp.async.cg.shared.global [%0], [%1], 16;" :: "r"(s), "l"(g));
}

// ---------------- kernel 0: merged setup (zero adjacency + W transpose/fp16) ----
__global__ void __launch_bounds__(256) setup_kernel(const float* __restrict__ W) {
    __shared__ float tile[32][33];
    if (blockIdx.x < 128) {
        for (int j = blockIdx.x * 256 + threadIdx.x; j < BB * NN * ADJ_WORDS; j += 128 * 256)
            g_adj[j] = 0u;
        return;
    }
    const int bid = blockIdx.x - 128;
    const int l   = bid >> 8;
    const int rem = bid & 255;
    const int n0  = (rem & 15) * 32;
    const int k0  = (rem >> 4) * 32;
    const int tx  = threadIdx.x & 31;
    const int ty  = threadIdx.x >> 5;

    #pragma unroll
    for (int i = 0; i < 4; i++)
        tile[ty + i * 8][tx] = W[(size_t)l * HH * HH + (size_t)(k0 + ty + i * 8) * HH + n0 + tx];
    __syncthreads();

    #pragma unroll
    for (int i = 0; i < 4; i++) {
        const int n = n0 + ty + i * 8;
        const int k = k0 + tx;
        g_Wh[(size_t)l * HH * HH + (size_t)n * HH + k] = __float2half_rn(tile[tx][ty + i * 8]);
    }
}

// ---------------- kernel 1: spatial binning (one block per batch) ----------------
__global__ void __launch_bounds__(256) bin_kernel(const float2* __restrict__ coords) {
    __shared__ int cnt[256];
    __shared__ int start[257];
    __shared__ uint16_t cellof[NN];
    const int b = blockIdx.x;
    const int tid = threadIdx.x;

    cnt[tid] = 0;
    __syncthreads();
    for (int i = tid; i < NN; i += 256) {
        const float2 c = coords[(size_t)b * NN + i];
        int cx = (int)(c.x * GRID); cx = cx < 0 ? 0 : (cx > 15 ? 15 : cx);
        int cy = (int)(c.y * GRID); cy = cy < 0 ? 0 : (cy > 15 ? 15 : cy);
        const int cell = cy * GRID + cx;
        cellof[i] = (uint16_t)cell;
        atomicAdd(&cnt[cell], 1);
    }
    __syncthreads();
    if (tid == 0) {
        int run = 0;
        for (int c = 0; c < 256; c++) { start[c] = run; run += cnt[c]; }
        start[256] = run;
    }
    __syncthreads();
    g_bin_start[b][tid] = start[tid];
    if (tid == 0) g_bin_start[b][256] = start[256];
    cnt[tid] = start[tid];            // reuse as scatter cursor
    __syncthreads();
    for (int i = tid; i < NN; i += 256) {
        const int cell = cellof[i];
        const int pos = atomicAdd(&cnt[cell], 1);
        g_bin_ids[b][pos] = (uint16_t)i;
    }
}

// ---------------- kernel 2: binned exact top-k + adjacency ----------------
// One thread per point; expanding cell rings with provable stop criterion.
__global__ void __launch_bounds__(256) topk_adj_kernel(const float2* __restrict__ coords) {
    __shared__ float2 sc[NN];          // 16 KB
    __shared__ int sstart[257];
    __shared__ uint16_t sids[NN];      // 4 KB
    const int b   = blockIdx.y;
    const int seg = blockIdx.x;
    const int tid = threadIdx.x;

    const float2* cb = coords + (size_t)b * NN;
    for (int i = tid; i < NN; i += 256) { sc[i] = cb[i]; sids[i] = g_bin_ids[b][i]; }
    if (tid < 128) { sstart[2*tid] = g_bin_start[b][2*tid]; sstart[2*tid+1] = g_bin_start[b][2*tid+1]; }
    if (tid == 0) sstart[256] = g_bin_start[b][256];
    __syncthreads();

    const int n = seg * 256 + tid;
    const float xn = sc[n].x, yn = sc[n].y;
    const float sqn = __fadd_rn(__fmul_rn(xn, xn), __fmul_rn(yn, yn));
    int cx = (int)(xn * GRID); cx = cx < 0 ? 0 : (cx > 15 ? 15 : cx);
    int cy = (int)(yn * GRID); cy = cy < 0 ? 0 : (cy > 15 ? 15 : cy);

    unsigned long long top[NSEL];
    #pragma unroll
    for (int j = 0; j < NSEL; j++) top[j] = ~0ull;

    #define SCAN_CELL(yy, xx) do {                                                     \
        const int c_ = (yy) * GRID + (xx);                                             \
        const int e_ = sstart[c_ + 1];                                                 \
        for (int j_ = sstart[c_]; j_ < e_; j_++) {                                     \
            const int m_ = sids[j_];                                                   \
            const float xm_ = sc[m_].x, ym_ = sc[m_].y;                                \
            const float sqm_ = __fadd_rn(__fmul_rn(xm_, xm_), __fmul_rn(ym_, ym_));    \
            const float dot_ = __fmaf_rn(yn, ym_, __fmul_rn(xn, xm_));                 \
            const float d2_  = __fsub_rn(__fadd_rn(sqn, sqm_), __fmul_rn(2.0f, dot_)); \
            uint32_t fb_ = __float_as_uint(d2_);                                       \
            fb_ = (fb_ & 0x80000000u) ? ~fb_ : (fb_ | 0x80000000u);                    \
            const unsigned long long k_ = ((unsigned long long)fb_ << 32) | (uint32_t)m_; \
            if (k_ < top[NSEL - 1]) {                                                  \
                top[NSEL - 1] = k_;                                                    \
                _Pragma("unroll")                                                      \
                for (int q_ = NSEL - 1; q_ > 0; q_--) {                                \
                    if (top[q_] < top[q_ - 1]) {                                       \
                        unsigned long long t_ = top[q_];                               \
                        top[q_] = top[q_ - 1]; top[q_ - 1] = t_;                       \
                    }                                                                  \
                }                                                                      \
            }                                                                          \
        }                                                                              \
    } while (0)

    for (int r = 1; r <= GRID; r++) {
        const int x0 = (cx - r < 0) ? 0 : cx - r;
        const int x1 = (cx + r > 15) ? 15 : cx + r;
        if (r == 1) {
            const int y0 = (cy - 1 < 0) ? 0 : cy - 1;
            const int y1 = (cy + 1 > 15) ? 15 : cy + 1;
            for (int yy = y0; yy <= y1; yy++)
                for (int xx = x0; xx <= x1; xx++) SCAN_CELL(yy, xx);
        } else {
            if (cy - r >= 0)  for (int xx = x0; xx <= x1; xx++) SCAN_CELL(cy - r, xx);
            if (cy + r <= 15) for (int xx = x0; xx <= x1; xx++) SCAN_CELL(cy + r, xx);
            const int yi0 = (cy - r + 1 < 0) ? 0 : cy - r + 1;
            const int yi1 = (cy + r - 1 > 15) ? 15 : cy + r - 1;
            if (cx - r >= 0)  for (int yy = yi0; yy <= yi1; yy++) SCAN_CELL(yy, cx - r);
            if (cx + r <= 15) for (int yy = yi0; yy <= yi1; yy++) SCAN_CELL(yy, cx + r);
        }
        // coverage -> done
        if (cx - r <= 0 && cx + r >= 15 && cy - r <= 0 && cy + r >= 15) break;
        // bound: min distance from point to the border of the examined region
        float bnd = 1e30f;
        if (cx - r > 0)  bnd = fminf(bnd, xn - (float)(cx - r) * CW);
        if (cx + r < 15) bnd = fminf(bnd, (float)(cx + r + 1) * CW - xn);
        if (cy - r > 0)  bnd = fminf(bnd, yn - (float)(cy - r) * CW);
        if (cy + r < 15) bnd = fminf(bnd, (float)(cy + r + 1) * CW - yn);
        if (top[NSEL - 1] != ~0ull) {
            const uint32_t fb8 = (uint32_t)(top[NSEL - 1] >> 32);
            const float kd = (fb8 & 0x80000000u) ? __uint_as_float(fb8 ^ 0x80000000u)
                                                 : __uint_as_float(~fb8);
            if (kd < bnd * bnd - 1e-4f) break;   // provably no closer point outside
        }
    }

    // write adjacency: drop rank 0, keep ranks 1..8
    #pragma unroll
    for (int rr = 1; rr < NSEL; rr++) {
        const int m = (int)(top[rr] & 0xffffffffu);
        atomicOr(&g_adj[((size_t)b * NN + n) * ADJ_WORDS + (m >> 5)], 1u << (m & 31));
        atomicOr(&g_adj[((size_t)b * NN + m) * ADJ_WORDS + (n >> 5)], 1u << (n & 31));
    }
}

// ---------------- kernel 3: sparse aggregation via smem neighbor list (R10) ------
__global__ void __launch_bounds__(128) agg_kernel(const float4* __restrict__ xin) {
    __shared__ uint32_t rowbits[ADJ_WORDS];
    __shared__ int s_off[ADJ_WORDS];
    __shared__ int s_nbr[512];
    __shared__ int s_cnt;
    const int b = blockIdx.y;
    const int n = blockIdx.x;
    const int t = threadIdx.x;

    const uint32_t* row = &g_adj[((size_t)b * NN + n) * ADJ_WORDS];
    if (t < ADJ_WORDS) rowbits[t] = row[t];
    __syncthreads();

    if (t == 0) {
        int off = 0;
        #pragma unroll
        for (int w = 0; w < ADJ_WORDS; w++) { s_off[w] = off; off += __popc(rowbits[w]); }
        s_cnt = off;
    }
    __syncthreads();
    if (t < ADJ_WORDS) {
        uint32_t bits = rowbits[t];
        int pos = s_off[t];
        while (bits) {
            const int bit = __ffs(bits) - 1;
            bits &= bits - 1;
            s_nbr[pos++] = (t << 5) + bit;
        }
    }
    __syncthreads();

    const int deg = s_cnt;
    const float4* xb = xin + (size_t)b * NN * (HH/4);
    float4 acc = make_float4(0.f, 0.f, 0.f, 0.f);
    for (int i = 0; i < deg; i++) {
        const float4 v = __ldg(&xb[(size_t)s_nbr[i] * (HH/4) + t]);
        acc.x += v.x; acc.y += v.y; acc.z += v.z; acc.w += v.w;
    }

    __half2 h01 = __halves2half2(__float2half_rn(acc.x), __float2half_rn(acc.y));
    __half2 h23 = __halves2half2(__float2half_rn(acc.z), __float2half_rn(acc.w));
    const size_t base = ((size_t)b * NN + n) * (HH/2) + 2 * t;
    ((__half2*)g_Ah)[base]     = h01;
    ((__half2*)g_Ah)[base + 1] = h23;
}

// ---------------- kernel 4: cp.async-pipelined fp16 GEMM + LN, K-chunk 64 (R10) --
#define STG      82944
#define SG_BIAS  165888
#define SG_GAMMA 167936
#define SG_BETA  169984
#define SG_PSUM  172032
#define SG_PSQ   174080
#define SG_MU    176128
#define SG_RS    176384
#define SM_TOTAL2 176640

__global__ void __launch_bounds__(512, 1) gemm_mma_kernel(
    const __half* __restrict__ Ah,
    const __half* __restrict__ Wh,
    const float* __restrict__ bl, const float* __restrict__ gl, const float* __restrict__ btl,
    const float* __restrict__ resid, float* __restrict__ out)
{
    extern __shared__ char smem[];
    const uint32_t sbase = smem_u32(smem);
    const int tid  = threadIdx.x;
    const int lane = tid & 31;
    const int wid  = tid >> 5;
    const int mwarp = wid >> 3;
    const int nwarp = wid & 7;
    const int row0 = blockIdx.x * 64;

    ((float*)(smem + SG_BIAS))[tid]  = __ldg(&bl[tid]);
    ((float*)(smem + SG_GAMMA))[tid] = __ldg(&gl[tid]);
    ((float*)(smem + SG_BETA))[tid]  = __ldg(&btl[tid]);

    float c[16][4];
    #pragma unroll
    for (int f = 0; f < 16; f++)
        #pragma unroll
        for (int q = 0; q < 4; q++) c[f][q] = 0.f;

    #define LOAD_CHUNK(chk, stg) do {                                              \
        const int kc0_ = (chk) * 64;                                               \
        const uint32_t sb_ = sbase + (stg) * STG;                                  \
        {                                                                          \
            const int r_ = tid >> 3, seg_ = tid & 7;                               \
            cpa16(sb_ + r_ * 144 + seg_ * 16,                                      \
                  Ah + (size_t)(row0 + r_) * HH + kc0_ + seg_ * 8);                \
        }                                                                          \
        _Pragma("unroll")                                                          \
        for (int i_ = 0; i_ < 8; i_++) {                                           \
            const int idx_ = tid + i_ * 512;                                       \
            const int r_ = idx_ >> 3, seg_ = idx_ & 7;                             \
            cpa16(sb_ + 9216 + r_ * 144 + seg_ * 16,                               \
                  Wh + (size_t)r_ * HH + kc0_ + seg_ * 8);                         \
        }                                                                          \
        asm volatile("cp.async.commit_group;");                                    \
    } while (0)

    LOAD_CHUNK(0, 0);

    for (int chk = 0; chk < 8; chk++) {
        if (chk + 1 < 8) {
            LOAD_CHUNK(chk + 1, (chk + 1) & 1);
            asm volatile("cp.async.wait_group 1;");
        } else {
            asm volatile("cp.async.wait_group 0;");
        }
        __syncthreads();

        const uint32_t sb = sbase + (chk & 1) * STG;
        #pragma unroll
        for (int ks = 0; ks < 4; ks++) {
            const int amat = lane >> 3;
            const int arow = (amat & 1) * 8 + (lane & 7);
            const int akb  = (ks * 16 + (amat >> 1) * 8) * 2;
            uint32_t ah[2][4], bb[8][2];
            #pragma unroll
            for (int mi = 0; mi < 2; mi++) {
                const uint32_t ra = mwarp * 32 + mi * 16 + arow;
                ldm_x4(ah[mi], sb + ra * 144 + akb);
            }
            const int bmat = lane >> 3;
            const int bn   = (bmat >> 1) * 8 + (lane & 7);
            const int bkb  = (ks * 16 + (bmat & 1) * 8) * 2;
            #pragma unroll
            for (int g = 0; g < 4; g++) {
                uint32_t r[4];
                ldm_x4(r, sb + 9216 + (uint32_t)(nwarp * 64 + g * 16 + bn) * 144 + bkb);
                bb[g*2][0] = r[0]; bb[g*2][1] = r[1];
                bb[g*2+1][0] = r[2]; bb[g*2+1][1] = r[3];
            }
            #pragma unroll
            for (int mi = 0; mi < 2; mi++)
                #pragma unroll
                for (int ni = 0; ni < 8; ni++) mma_fp16(c[mi*8+ni], ah[mi], bb[ni]);
        }
        __syncthreads();
    }

    // ---------------- epilogue ----------------
    float* bias_s  = (float*)(smem + SG_BIAS);
    float* gamma_s = (float*)(smem + SG_GAMMA);
    float* beta_s  = (float*)(smem + SG_BETA);
    float* psum_s  = (float*)(smem + SG_PSUM);
    float* psq_s   = (float*)(smem + SG_PSQ);
    float* mu_s    = (float*)(smem + SG_MU);
    float* rs_s    = (float*)(smem + SG_RS);

    float ps[2][2] = {{0.f,0.f},{0.f,0.f}};
    float pq[2][2] = {{0.f,0.f},{0.f,0.f}};
    #pragma unroll
    for (int mi = 0; mi < 2; mi++)
        #pragma unroll
        for (int ni = 0; ni < 8; ni++) {
            const int f = mi*8 + ni;
            #pragma unroll
            for (int h = 0; h < 2; h++)
                #pragma unroll
                for (int j = 0; j < 2; j++) {
                    const int col = nwarp*64 + ni*8 + (lane & 3)*2 + j;
                    const float v = c[f][h*2+j] + bias_s[col];
                    c[f][h*2+j] = v;
                    ps[mi][h] += v;
                    pq[mi][h] += v * v;
                }
        }
    #pragma unroll
    for (int mi = 0; mi < 2; mi++)
        #pragma unroll
        for (int h = 0; h < 2; h++) {
            #pragma unroll
            for (int off = 1; off < 4; off <<= 1) {
                ps[mi][h] += __shfl_xor_sync(0xffffffffu, ps[mi][h], off);
                pq[mi][h] += __shfl_xor_sync(0xffffffffu, pq[mi][h], off);
            }
        }
    if ((lane & 3) == 0) {
        #pragma unroll
        for (int mi = 0; mi < 2; mi++)
            #pragma unroll
            for (int h = 0; h < 2; h++) {
                const int rl = mwarp*32 + mi*16 + h*8 + (lane >> 2);
                psum_s[rl*8 + nwarp] = ps[mi][h];
                psq_s [rl*8 + nwarp] = pq[mi][h];
            }
    }
    __syncthreads();
    if (tid < 64) {
        float s = 0.f, q = 0.f;
        #pragma unroll
        for (int w = 0; w < 8; w++) { s += psum_s[tid*8 + w]; q += psq_s[tid*8 + w]; }
        const float mu = s * (1.0f / HH);
        const float var = q * (1.0f / HH) - mu * mu;
        mu_s[tid] = mu;
        rs_s[tid] = rsqrtf(var + LN_EPS);
    }
    __syncthreads();

    #pragma unroll
    for (int mi = 0; mi < 2; mi++)
        #pragma unroll
        for (int h = 0; h < 2; h++) {
            const int rl = mwarp*32 + mi*16 + h*8 + (lane >> 2);
            const int grow = row0 + rl;
            const float mu = mu_s[rl];
            const float rs = rs_s[rl];
            #pragma unroll
            for (int ni = 0; ni < 8; ni++) {
                const int f = mi*8 + ni;
                const int col = nwarp*64 + ni*8 + (lane & 3)*2;
                float2 o;
                o.x = fmaxf((c[f][h*2+0] - mu) * rs * gamma_s[col]   + beta_s[col],   0.f);
                o.y = fmaxf((c[f][h*2+1] - mu) * rs * gamma_s[col+1] + beta_s[col+1], 0.f);
                if (resid != nullptr) {
                    const float2 rv = __ldg((const float2*)&resid[(size_t)grow * HH + col]);
                    o.x += rv.x; o.y += rv.y;
                }
                *(float2*)&out[(size_t)grow * HH + col] = o;
            }
        }
}

// ---------------- launcher ----------------
extern "C" void kernel_launch(void* const* d_in, const int* in_sizes, int n_in,
                              void* d_out, int out_size) {
    (void)in_sizes; (void)n_in; (void)out_size;
    const float*  node_features = (const float*)d_in[0];   // [8,2048,512]
    const float2* coords        = (const float2*)d_in[1];  // [8,2048,2]
    const float*  W             = (const float*)d_in[2];   // [3,512,512]
    const float*  bvec          = (const float*)d_in[3];   // [3,512]
    const float*  gamma         = (const float*)d_in[4];   // [3,512]
    const float*  beta          = (const float*)d_in[5];   // [3,512]
    float*        outp          = (float*)d_out;           // [8,2048,512]

    float4* gx;  cudaGetSymbolAddress((void**)&gx,  g_x4);
    __half *ah, *wh;
    cudaGetSymbolAddress((void**)&ah, g_Ah);
    cudaGetSymbolAddress((void**)&wh, g_Wh);

    cudaFuncSetAttribute(gemm_mma_kernel, cudaFuncAttributeMaxDynamicSharedMemorySize, SM_TOTAL2);

    setup_kernel<<<896, 256>>>(W);
    bin_kernel<<<BB, 256>>>(coords);
    topk_adj_kernel<<<dim3(NN / 256, BB), 256>>>(coords);

    for (int l = 0; l < NLAYERS; l++) {
        const float4* xin = (l == 0) ? (const float4*)node_features : (const float4*)gx;
        agg_kernel<<<dim3(NN, BB), 128>>>(xin);

        const float* resid = (l == 0) ? nullptr : (const float*)gx;
        float* out = (l == NLAYERS - 1) ? outp : (float*)gx;
        gemm_mma_kernel<<<MTOT / 64, 512, SM_TOTAL2>>>(
            ah, wh + (size_t)l * HH * HH,
            bvec + (size_t)l * HH, gamma + (size_t)l * HH, beta + (size_t)l * HH,
            resid, out);
    }
}